// round 17
// baseline (speedup 1.0000x reference)
#include <cuda_runtime.h>
#include <cuda_bf16.h>
#include <cstdint>

#define N_TOK 8192
#define D     512
#define E     16
#define H     2048
#define CAP   1024
#define ROWS_PER_E 2048   // b * CAP

// ---------------- scratch (static device globals; no allocation) ----------------
__device__ uint4  g_einh4[(size_t)E * ROWS_PER_E * D / 8];   // ein hi bf16
__device__ uint4  g_einl4[(size_t)E * ROWS_PER_E * D / 8];   // ein lo bf16
__device__ uint4  g_hidh4[(size_t)E * ROWS_PER_E * H / 8];   // hid hi bf16
__device__ uint4  g_hidl4[(size_t)E * ROWS_PER_E * H / 8];   // hid lo bf16
__device__ uint4  g_w1h4 [(size_t)E * D * H / 8];            // w1 hi bf16 [e][K][N]
__device__ uint4  g_w1l4 [(size_t)E * D * H / 8];
__device__ uint4  g_w2h4 [(size_t)E * H * D / 8];            // w2 hi bf16 [e][K][N]
__device__ uint4  g_w2l4 [(size_t)E * H * D / 8];
__device__ float4 g_eout4[(size_t)E * ROWS_PER_E * D / 4];   // expert outputs f32
__device__ int   g_i1[N_TOK], g_i2[N_TOK];
__device__ int   g_s1[N_TOK], g_s2[N_TOK];
__device__ float g_g1[N_TOK], g_g2[N_TOK];
__device__ int   g_used[E * 2];

// ---------------- small helpers ----------------
__device__ __forceinline__ uint32_t smem_to_u32(const void* p) {
    uint32_t a;
    asm("{ .reg .u64 t; cvta.to.shared.u64 t, %1; cvt.u32.u64 %0, t; }" : "=r"(a) : "l"(p));
    return a;
}
__device__ __forceinline__ void ldmx4(uint32_t* r, uint32_t addr) {
    asm volatile("ldmatrix.sync.aligned.m8n8.x4.shared.b16 {%0,%1,%2,%3}, [%4];"
                 : "=r"(r[0]), "=r"(r[1]), "=r"(r[2]), "=r"(r[3]) : "r"(addr));
}
__device__ __forceinline__ void ldmx4t(uint32_t* r, uint32_t addr) {
    asm volatile("ldmatrix.sync.aligned.m8n8.x4.trans.shared.b16 {%0,%1,%2,%3}, [%4];"
                 : "=r"(r[0]), "=r"(r[1]), "=r"(r[2]), "=r"(r[3]) : "r"(addr));
}
__device__ __forceinline__ void mma16816(float* c, const uint32_t* a, const uint32_t* b) {
    asm volatile("mma.sync.aligned.m16n8k16.row.col.f32.bf16.bf16.f32 "
                 "{%0,%1,%2,%3}, {%4,%5,%6,%7}, {%8,%9}, {%0,%1,%2,%3};"
                 : "+f"(c[0]), "+f"(c[1]), "+f"(c[2]), "+f"(c[3])
                 : "r"(a[0]), "r"(a[1]), "r"(a[2]), "r"(a[3]), "r"(b[0]), "r"(b[1]));
}
// pack two floats into (hi bf16 x2) and (lo bf16 x2) words
__device__ __forceinline__ void split2(float a, float b, uint32_t& hi, uint32_t& lo) {
    __nv_bfloat16 h0 = __float2bfloat16(a);
    __nv_bfloat16 h1 = __float2bfloat16(b);
    __nv_bfloat16 l0 = __float2bfloat16(a - __bfloat162float(h0));
    __nv_bfloat16 l1 = __float2bfloat16(b - __bfloat162float(h1));
    __nv_bfloat162 hh = __halves2bfloat162(h0, h1);
    __nv_bfloat162 ll = __halves2bfloat162(l0, l1);
    hi = *(uint32_t*)&hh;
    lo = *(uint32_t*)&ll;
}

// ---------------- 1) gating (identical to R13/R15 pass) ----------------
__global__ void gating_kernel(const float* __restrict__ x, const float* __restrict__ wg)
{
    __shared__ float wgs[E][D];
    const int tid = threadIdx.x;
    for (int i = tid; i < D * E; i += blockDim.x) wgs[i & (E - 1)][i >> 4] = wg[i];
    __syncthreads();

    const int lane = tid & 31, warp = tid >> 5;
    const int tok = blockIdx.x * (blockDim.x >> 5) + warp;
    const float* xp = x + (size_t)tok * D;

    float acc[E];
#pragma unroll
    for (int e = 0; e < E; e++) acc[e] = 0.f;
    for (int d = lane; d < D; d += 32) {
        const float xv = xp[d];
#pragma unroll
        for (int e = 0; e < E; e++) acc[e] = fmaf(xv, wgs[e][d], acc[e]);
    }
#pragma unroll
    for (int off = 16; off; off >>= 1)
#pragma unroll
        for (int e = 0; e < E; e++) acc[e] += __shfl_xor_sync(0xffffffffu, acc[e], off);

    if (lane == 0) {
        float m = acc[0];
#pragma unroll
        for (int e = 1; e < E; e++) m = fmaxf(m, acc[e]);
        float p[E]; float s = 0.f;
#pragma unroll
        for (int e = 0; e < E; e++) { p[e] = expf(acc[e] - m); s += p[e]; }
        int i1 = 0; float v1 = p[0];
#pragma unroll
        for (int e = 1; e < E; e++) if (p[e] > v1) { v1 = p[e]; i1 = e; }
        int i2 = -1; float v2 = -1.f;
#pragma unroll
        for (int e = 0; e < E; e++) if (e != i1 && p[e] > v2) { v2 = p[e]; i2 = e; }
        const float inv = 1.f / s;
        const float gate1 = v1 * inv, gate2 = v2 * inv;
        const float denom = gate1 + gate2 + 1e-9f;
        g_i1[tok] = i1;            g_i2[tok] = i2;
        g_g1[tok] = gate1 / denom; g_g2[tok] = gate2 / denom;
    }
}

// ---------------- 2) scheduler (identical to R13/R15 pass) ----------------
__global__ void schedule_kernel()
{
    const int b    = blockIdx.x;
    const int t    = threadIdx.x;
    const int lane = t & 31, warp = t >> 5;
    __shared__ int warpTot[16][E];
    __shared__ int warpPre[16][E];
    __shared__ int totS[E];
    __shared__ int baseS[E];
    const int tokBase = b * 4096 + t * 8;

    for (int phase = 0; phase < 2; phase++) {
        const int* gidx = phase ? g_i2 : g_i1;
        int eidx[8];
#pragma unroll
        for (int k = 0; k < 8; k++) eidx[k] = gidx[tokBase + k];

        int inc[E], myc[E];
#pragma unroll
        for (int e = 0; e < E; e++) inc[e] = 0;
#pragma unroll
        for (int k = 0; k < 8; k++)
#pragma unroll
            for (int e = 0; e < E; e++) inc[e] += (eidx[k] == e);
#pragma unroll
        for (int e = 0; e < E; e++) myc[e] = inc[e];

        for (int off = 1; off < 32; off <<= 1) {
#pragma unroll
            for (int e = 0; e < E; e++) {
                const int v = __shfl_up_sync(0xffffffffu, inc[e], off);
                if (lane >= off) inc[e] += v;
            }
        }
        if (lane == 31) {
#pragma unroll
            for (int e = 0; e < E; e++) warpTot[warp][e] = inc[e];
        }
        __syncthreads();
        {
            const int v = (lane < 16) ? warpTot[lane][warp] : 0;
            int iv = v;
            for (int off = 1; off < 16; off <<= 1) {
                const int u = __shfl_up_sync(0xffffffffu, iv, off);
                if (lane >= off) iv += u;
            }
            if (lane < 16)  warpPre[lane][warp] = iv - v;
            if (lane == 15) totS[warp] = iv;
        }
        __syncthreads();

        int prefix[E];
#pragma unroll
        for (int e = 0; e < E; e++)
            prefix[e] = (phase ? baseS[e] : 0) + warpPre[warp][e] + (inc[e] - myc[e]);

#pragma unroll
        for (int k = 0; k < 8; k++) {
            int pos = 0;
#pragma unroll
            for (int j = 0; j < k; j++) pos += (eidx[j] == eidx[k]);
#pragma unroll
            for (int e = 0; e < E; e++) pos += (eidx[k] == e) ? prefix[e] : 0;
            const bool kept = pos < CAP;
            if (phase == 0) {
                g_s1[tokBase + k] = kept ? pos : -1;
                if (!kept) g_g1[tokBase + k] = 0.f;
            } else {
                g_s2[tokBase + k] = kept ? pos : -1;
                if (!kept) g_g2[tokBase + k] = 0.f;
            }
        }

        if (phase == 0) {
            __syncthreads();
            if (t < E) baseS[t] = min(totS[t], CAP);
            __syncthreads();
        } else {
            if (t < E) g_used[t * 2 + b] = baseS[t] + min(totS[t], CAP - baseS[t]);
        }
    }
}

// ---------------- 3) gather: tokens -> expert rows, bf16 hi/lo split ----------------
__global__ void gather_kernel(const float4* __restrict__ x4)
{
    const int warp = threadIdx.x >> 5, lane = threadIdx.x & 31;
    const int a = blockIdx.x * 8 + warp;
    const int tok = a >> 1, which = a & 1;
    const int slot = which ? g_s2[tok] : g_s1[tok];
    if (slot < 0) return;
    const int e = which ? g_i2[tok] : g_i1[tok];
    const int b = tok >> 12;
    const float4* src = x4 + (size_t)tok * (D / 4);
    const size_t base = (((size_t)e * 2 + b) * CAP + slot) * D;
    uint2* dh = (uint2*)((__nv_bfloat16*)g_einh4 + base);
    uint2* dl = (uint2*)((__nv_bfloat16*)g_einl4 + base);
#pragma unroll
    for (int i = lane; i < D / 4; i += 32) {
        const float4 v = src[i];
        uint32_t h0, l0, h1, l1;
        split2(v.x, v.y, h0, l0);
        split2(v.z, v.w, h1, l1);
        dh[i] = make_uint2(h0, h1);
        dl[i] = make_uint2(l0, l1);
    }
}

// ---------------- 3b) weight split (elementwise, no transpose): W f32 -> hi/lo bf16 ----------------
// Destination arrays resolved from __device__ globals INSIDE device code.
template<int WHICH>
__global__ void wsplit_kernel(const float4* __restrict__ W)
{
    uint2* __restrict__ hi = (uint2*)(WHICH ? (void*)g_w2h4 : (void*)g_w1h4);
    uint2* __restrict__ lo = (uint2*)(WHICH ? (void*)g_w2l4 : (void*)g_w1l4);
    const size_t i = (size_t)blockIdx.x * blockDim.x + threadIdx.x;
    const float4 v = W[i];
    uint32_t h0, l0, h1, l1;
    split2(v.x, v.y, h0, l0);
    split2(v.z, v.w, h1, l1);
    hi[i] = make_uint2(h0, h1);
    lo[i] = make_uint2(l0, l1);
}

// ---------------- 4) HMMA bf16x3 GEMM on pre-split bf16, 1-barrier pipeline ----------------
// WHICH==0: hid = relu(ein @ w1)   KDIM=512   NDIM=2048
// WHICH==1: eout = hid @ w2        KDIM=2048  NDIM=512
// CTA tile 128x128, K-chunk 16, 8 warps (4m x 2n), warp tile 32x64.
// smem layout + fragment mappings byte-identical to R15 (proven). Loader is now pure
// uint4 LDG/STS of pre-split bf16 (no cvt/sub work in the hot loop).
#define A_ST   48
#define ATILE  (128 * A_ST)              // 6144
#define B_ST   272
#define BTILE  (16 * B_ST)               // 4352
#define B_OFF  (2 * ATILE)               // 12288
#define BUFSZ  (B_OFF + 2 * BTILE)       // 20992

template<int KDIM, int NDIM, int WHICH>
__global__ void __launch_bounds__(256, 2) hmma_ffn_kernel()
{
    const int e  = blockIdx.z;
    const int m0 = blockIdx.y * 128;
    const int n0 = blockIdx.x * 128;
    if ((m0 & 1023) >= g_used[e * 2 + (m0 >> 10)]) return;

    __shared__ alignas(16) char sbuf[2 * BUFSZ];
    const uint32_t sb = smem_to_u32(sbuf);
    const int tid = threadIdx.x, wid = tid >> 5, lane = tid & 31;
    const int warp_m = wid >> 1, warp_n = wid & 1;

    const __nv_bfloat16* __restrict__ Ah =
        (const __nv_bfloat16*)(WHICH ? (const void*)g_hidh4 : (const void*)g_einh4) + (size_t)e * ROWS_PER_E * KDIM;
    const __nv_bfloat16* __restrict__ Al =
        (const __nv_bfloat16*)(WHICH ? (const void*)g_hidl4 : (const void*)g_einl4) + (size_t)e * ROWS_PER_E * KDIM;
    const __nv_bfloat16* __restrict__ Bh =
        (const __nv_bfloat16*)(WHICH ? (const void*)g_w2h4 : (const void*)g_w1h4) + (size_t)e * KDIM * NDIM;
    const __nv_bfloat16* __restrict__ Bl =
        (const __nv_bfloat16*)(WHICH ? (const void*)g_w2l4 : (const void*)g_w1l4) + (size_t)e * KDIM * NDIM;

    float acc[2][8][4];
#pragma unroll
    for (int i = 0; i < 2; i++)
#pragma unroll
        for (int j = 0; j < 8; j++)
#pragma unroll
            for (int k = 0; k < 4; k++) acc[i][j][k] = 0.f;

    const int NC = KDIM / 16;
    // loader geometry: A chunk = 128 rows x 2 uint4; B chunk = 16 k-rows x 16 uint4
    const int aRow = tid >> 1, aSeg = tid & 1;
    const int bKr  = tid >> 4, bNs = tid & 15;

    uint4 pah, pal, pbh, pbl;
    auto gload = [&](int c) {
        const size_t ga = (size_t)(m0 + aRow) * KDIM + c * 16 + aSeg * 8;
        const size_t gb = (size_t)(c * 16 + bKr) * NDIM + n0 + bNs * 8;
        pah = *(const uint4*)(Ah + ga);
        pal = *(const uint4*)(Al + ga);
        pbh = *(const uint4*)(Bh + gb);
        pbl = *(const uint4*)(Bl + gb);
    };
    auto sstore = [&](int c) {
        char* bp = sbuf + (c & 1) * BUFSZ;
        *(uint4*)(bp + aRow * A_ST + aSeg * 16)                 = pah;
        *(uint4*)(bp + ATILE + aRow * A_ST + aSeg * 16)         = pal;
        *(uint4*)(bp + B_OFF + bKr * B_ST + bNs * 16)           = pbh;
        *(uint4*)(bp + B_OFF + BTILE + bKr * B_ST + bNs * 16)   = pbl;
    };

    // prologue: buf0 filled; regs hold chunk 1
    gload(0);
    sstore(0);
    if (NC > 1) gload(1);
    __syncthreads();

#pragma unroll 1
    for (int c = 0; c < NC; c++) {
        const uint32_t bb = sb + (c & 1) * BUFSZ;

        // A fragments (row-major, non-trans ldmatrix), mapping verified R13-R15
        uint32_t ah[2][4], al[2][4];
#pragma unroll
        for (int mf = 0; mf < 2; mf++) {
            const uint32_t ao = bb
                + (uint32_t)(warp_m * 32 + mf * 16 + (lane & 15)) * A_ST
                + (uint32_t)(lane >> 4) * 16;
            ldmx4(ah[mf], ao);
            ldmx4(al[mf], ao + ATILE);
        }

        // Overlapped with MMAs: store chunk c+1 into the OTHER buffer, refill regs
        // with chunk c+2. Legal per R14/15: buf(c+1) readers finished at the
        // end-of-iteration barrier of iter c-1.
        if (c + 1 < NC) sstore(c + 1);
        if (c + 2 < NC) gload(c + 2);

        // B fragments + MMAs; accumulator round-robin -> RAW distance 4.
        const int q = lane >> 3;
#pragma unroll
        for (int np = 0; np < 4; np++) {
            const uint32_t bo = bb + B_OFF
                + (uint32_t)((q & 1) * 8 + (lane & 7)) * B_ST
                + (uint32_t)(warp_n * 64 + np * 16 + (q >> 1) * 8) * 2;
            uint32_t t[4], u[4];
            ldmx4t(t, bo);           // bh pair for nf = 2np, 2np+1
            ldmx4t(u, bo + BTILE);   // bl pair
            mma16816(acc[0][2 * np],     ah[0], &t[0]);
            mma16816(acc[0][2 * np + 1], ah[0], &t[2]);
            mma16816(acc[1][2 * np],     ah[1], &t[0]);
            mma16816(acc[1][2 * np + 1], ah[1], &t[2]);
            mma16816(acc[0][2 * np],     al[0], &t[0]);
            mma16816(acc[0][2 * np + 1], al[0], &t[2]);
            mma16816(acc[1][2 * np],     al[1], &t[0]);
            mma16816(acc[1][2 * np + 1], al[1], &t[2]);
            mma16816(acc[0][2 * np],     ah[0], &u[0]);
            mma16816(acc[0][2 * np + 1], ah[0], &u[2]);
            mma16816(acc[1][2 * np],     ah[1], &u[0]);
            mma16816(acc[1][2 * np + 1], ah[1], &u[2]);
        }
        __syncthreads();   // buf(c+1) ready; all warps done reading buf(c)
    }

    // ---- epilogue ----
    const int er0 = m0 + warp_m * 32 + (lane >> 2);
    const int ec0 = n0 + warp_n * 64 + 2 * (lane & 3);
#pragma unroll
    for (int mf = 0; mf < 2; mf++) {
#pragma unroll
        for (int nf = 0; nf < 8; nf++) {
#pragma unroll
            for (int half = 0; half < 2; half++) {
                const int rr = er0 + mf * 16 + half * 8;
                const int cc = ec0 + nf * 8;
                const float v0 = acc[mf][nf][2 * half];
                const float v1 = acc[mf][nf][2 * half + 1];
                if (WHICH == 0) {
                    // relu + split to bf16 hi/lo for GEMM2's pre-split A
                    const float r0v = fmaxf(v0, 0.f), r1v = fmaxf(v1, 0.f);
                    uint32_t hh, ll;
                    split2(r0v, r1v, hh, ll);
                    const size_t o = ((size_t)e * ROWS_PER_E + rr) * NDIM + cc;
                    *(uint32_t*)((__nv_bfloat16*)g_hidh4 + o) = hh;
                    *(uint32_t*)((__nv_bfloat16*)g_hidl4 + o) = ll;
                } else {
                    const size_t o = ((size_t)e * ROWS_PER_E + rr) * NDIM + cc;
                    *(float2*)((float*)g_eout4 + o) = make_float2(v0, v1);
                }
            }
        }
    }
}

// ---------------- 5) combine (identical to R13/R15 pass) ----------------
__global__ void combine_kernel(float4* __restrict__ out4)
{
    const int warp = threadIdx.x >> 5, lane = threadIdx.x & 31;
    const int tok = blockIdx.x * 8 + warp;
    const int b = tok >> 12;
    const int s1v = g_s1[tok], s2v = g_s2[tok];
    const float g1 = g_g1[tok], g2 = g_g2[tok];
    const bool h1 = s1v >= 0, h2 = s2v >= 0;
    const float4* p1 = g_eout4 + (((size_t)g_i1[tok] * 2 + b) * CAP + (h1 ? s1v : 0)) * (D / 4);
    const float4* p2 = g_eout4 + (((size_t)g_i2[tok] * 2 + b) * CAP + (h2 ? s2v : 0)) * (D / 4);
    float4* op = out4 + (size_t)tok * (D / 4);
#pragma unroll
    for (int i = lane; i < D / 4; i += 32) {
        float4 r = make_float4(0.f, 0.f, 0.f, 0.f);
        if (h1) { const float4 a = p1[i]; r.x = fmaf(g1, a.x, r.x); r.y = fmaf(g1, a.y, r.y);
                  r.z = fmaf(g1, a.z, r.z); r.w = fmaf(g1, a.w, r.w); }
        if (h2) { const float4 a = p2[i]; r.x = fmaf(g2, a.x, r.x); r.y = fmaf(g2, a.y, r.y);
                  r.z = fmaf(g2, a.z, r.z); r.w = fmaf(g2, a.w, r.w); }
        op[i] = r;
    }
}

// ---------------- launcher ----------------
extern "C" void kernel_launch(void* const* d_in, const int* in_sizes, int n_in,
                              void* d_out, int out_size)
{
    const float* x  = (const float*)d_in[0];   // [2,4096,512]
    const float* wg = (const float*)d_in[1];   // [512,16]
    const float* w1 = (const float*)d_in[2];   // [16,512,2048]
    const float* w2 = (const float*)d_in[3];   // [16,2048,512]
    float4* out = (float4*)d_out;              // [2,4096,512]

    gating_kernel<<<N_TOK / 8, 256>>>(x, wg);
    schedule_kernel<<<2, 512>>>();
    gather_kernel<<<16384 / 8, 256>>>((const float4*)x);

    // elementwise weight splits: E*D*H/4 float4 elements each (identical sizes)
    const int WBLK = (E * D * H / 4) / 256;    // 16384 blocks
    wsplit_kernel<0><<<WBLK, 256>>>((const float4*)w1);
    wsplit_kernel<1><<<WBLK, 256>>>((const float4*)w2);

    hmma_ffn_kernel<D, H, 0><<<dim3(H / 128, ROWS_PER_E / 128, E), 256>>>();
    hmma_ffn_kernel<H, D, 1><<<dim3(D / 128, ROWS_PER_E / 128, E), 256>>>();

    combine_kernel<<<N_TOK / 8, 256>>>(out);
}